// round 6
// baseline (speedup 1.0000x reference)
#include <cuda_runtime.h>
#include <math.h>

#define NB   32
#define D    128
#define L    2048
#define WIN  63          // half-window: |i-j| <= 63
#define WSZ  127         // window size
#define XS_STR 132       // smem stride for tf32 fragment tiles (k_qkv/k_out)

// k_aft tiling
#define TI2  32                  // i-tile
#define JR2  (TI2 + 2*WIN)       // 158 j-rows in union window
#define KP   160                 // padded K for MMA
#define ASTR 164                 // smem stride (conflict-free frag loads)

typedef unsigned int       u32;
typedef unsigned long long u64;

// ---- tf32 helpers ----
__device__ __forceinline__ float tf32r(float v) {
    u32 u; asm("cvt.rna.tf32.f32 %0, %1;" : "=r"(u) : "f"(v));
    return __uint_as_float(u);
}
__device__ __forceinline__ void mma8(float4& d, u32 a0, u32 a1, u32 a2, u32 a3,
                                     u32 b0, u32 b1) {
    asm("mma.sync.aligned.m16n8k8.row.col.f32.tf32.tf32.f32 "
        "{%0,%1,%2,%3},{%4,%5,%6,%7},{%8,%9},{%0,%1,%2,%3};"
        : "+f"(d.x), "+f"(d.y), "+f"(d.z), "+f"(d.w)
        : "r"(a0), "r"(a1), "r"(a2), "r"(a3), "r"(b0), "r"(b1));
}
__device__ __forceinline__ u32 fb(float v) { return __float_as_uint(v); }

// ---------------- scratch (device globals; no allocation) ----------------
__device__ float g_sq [NB*L*D];   // sigmoid(q)
__device__ float g_ek [NB*L*D];   // exp(k)
__device__ float g_ekv[NB*L*D];   // first v, then exp(k)*v (in-place in k_sums)
__device__ float g_y  [NB*L*D];   // y before out-proj
__device__ float g_w  [L*WSZ];    // exp(pos_bias)-1 on the band (0 off-edge)
__device__ float g_partN[16*NB*D];
__device__ float g_partD[16*NB*D];

// ---------------- K0: band weights ----------------
__global__ void k_window(const float* __restrict__ pos_bias) {
    int i  = blockIdx.x;
    int jo = threadIdx.x;
    if (jo < WSZ) {
        int j = i - WIN + jo;
        float val = 0.f;
        if (j >= 0 && j < L) val = expf(pos_bias[(size_t)i * L + j]) - 1.f;
        g_w[i * WSZ + jo] = val;
    }
}

// ---------------- K1: QKV projection via mma.sync tf32 ----------
__global__ void k_qkv(const float* __restrict__ x,
                      const float* __restrict__ Wq, const float* __restrict__ bq,
                      const float* __restrict__ Wk, const float* __restrict__ bk,
                      const float* __restrict__ Wv, const float* __restrict__ bv) {
    extern __shared__ float sm[];
    float* xs = sm;                 // [64][XS_STR]  A: xs[l][c] (tf32)
    float* wt = sm + 64 * XS_STR;   // [128][XS_STR] B: wt[d][c] = W[c][d] (tf32)
    const int proj  = blockIdx.x;
    const int lbase = blockIdx.y * 64;
    const int n     = blockIdx.z;
    const float* Wm = (proj == 0) ? Wq : (proj == 1) ? Wk : Wv;
    const float* bm = (proj == 0) ? bq : (proj == 1) ? bk : bv;
    const int tid = threadIdx.x;

    for (int idx = tid; idx < 128 * 64; idx += 256) {
        int c = idx >> 6, l = idx & 63;
        xs[l * XS_STR + c] = tf32r(x[(size_t)n * D * L + (size_t)c * L + lbase + l]);
    }
    for (int idx = tid; idx < 128 * 128; idx += 256) {
        int c = idx >> 7, d = idx & 127;
        wt[d * XS_STR + c] = tf32r(Wm[c * 128 + d]);
    }
    __syncthreads();

    const int lane = tid & 31, w = tid >> 5;
    const int mbase = (w & 3) * 16;
    const int nbase = (w >> 2) * 64;
    const int t4 = lane >> 2, tq = lane & 3;

    float4 acc[8];
    #pragma unroll
    for (int i = 0; i < 8; i++) acc[i] = make_float4(0.f, 0.f, 0.f, 0.f);

    const float* arow0 = &xs[(mbase + t4) * XS_STR + tq];
    const float* arow1 = arow0 + 8 * XS_STR;
    #pragma unroll
    for (int k0 = 0; k0 < 128; k0 += 8) {
        u32 a0 = fb(arow0[k0]),     a2 = fb(arow0[k0 + 4]);
        u32 a1 = fb(arow1[k0]),     a3 = fb(arow1[k0 + 4]);
        #pragma unroll
        for (int nt = 0; nt < 8; nt++) {
            const float* bp = &wt[(nbase + nt * 8 + t4) * XS_STR + k0 + tq];
            mma8(acc[nt], a0, a1, a2, a3, fb(bp[0]), fb(bp[4]));
        }
    }

    const int row0 = mbase + t4, row1 = row0 + 8;
    #pragma unroll
    for (int nt = 0; nt < 8; nt++) {
        int cb = nbase + nt * 8 + 2 * tq;
        float b0 = bm[cb], b1 = bm[cb + 1];
        float r[4] = {acc[nt].x + b0, acc[nt].y + b1,
                      acc[nt].z + b0, acc[nt].w + b1};
        if (proj == 0) {
            #pragma unroll
            for (int e = 0; e < 4; e++) r[e] = 1.f / (1.f + expf(-r[e]));
        } else if (proj == 1) {
            #pragma unroll
            for (int e = 0; e < 4; e++) r[e] = expf(r[e]);
        }
        float* dst = (proj == 0) ? g_sq : (proj == 1) ? g_ek : g_ekv;
        size_t o0 = (size_t)n * L * D + (size_t)(lbase + row0) * D + cb;
        size_t o1 = (size_t)n * L * D + (size_t)(lbase + row1) * D + cb;
        *(float2*)&dst[o0] = make_float2(r[0], r[1]);
        *(float2*)&dst[o1] = make_float2(r[2], r[3]);
    }
}

// ---------------- K2: partial column sums; ekv = ek*v in place ----------
__global__ void k_sums() {
    const int n = blockIdx.x, chunk = blockIdx.y, d = threadIdx.x;
    float sn = 0.f, sd = 0.f;
    size_t base = (size_t)n * L * D + d;
    const int l0 = chunk * 128;
    for (int l = l0; l < l0 + 128; l++) {
        size_t off = base + (size_t)l * D;
        float e  = g_ek[off];
        float v  = g_ekv[off];
        float ev = e * v;
        g_ekv[off] = ev;
        sn += ev; sd += e;
    }
    g_partN[(chunk * NB + n) * D + d] = sn;
    g_partD[(chunk * NB + n) * D + d] = sd;
}

// ---------------- K3: banded AFT pass as tf32 tensor-core GEMM ----------
// C[32 i][256 c] = Wb[32][KP] @ X[KP][256]   (c<128: num vs ekv, c>=128: den vs ek)
// grid (L/TI2=64, NB), 256 threads
// smem = (256*ASTR + TI2*ASTR + 256)*4 = 189952 B
__global__ void k_aft() {
    extern __shared__ float sm[];
    float* xt  = sm;                        // [256 c][ASTR r]  B-operand (tf32)
    float* wb  = sm + 256 * ASTR;           // [32 il][ASTR r]  A-operand (tf32)
    float* ssn = sm + (256 + TI2) * ASTR;   // [128] S_num (fp32)
    float* ssd = ssn + 128;                 // [128] S_den (fp32)
    const int n     = blockIdx.y;
    const int ibase = blockIdx.x * TI2;
    const int tid   = threadIdx.x;
    const int jlo   = ibase - WIN;

    // fused global-sum reduction (fp32 exact)
    if (tid < 128) {
        float sn = 0.f, sd = 0.f;
        #pragma unroll
        for (int c = 0; c < 16; c++) {
            sn += g_partN[(c * NB + n) * D + tid];
            sd += g_partD[(c * NB + n) * D + tid];
        }
        ssn[tid] = sn; ssd[tid] = sd;
    }

    // fill X^T: xt[c][r] = (c<128 ? ekv : ek)[j= jlo+r][c%128], tf32, 0 off-edge
    for (int idx = tid; idx < KP * 256; idx += 256) {
        int r = idx >> 8, c = idx & 255;
        int j = jlo + r;
        float v = 0.f;
        if (r < JR2 && j >= 0 && j < L) {
            size_t off = (size_t)n * L * D + (size_t)j * D;
            v = (c < 128) ? g_ekv[off + c] : g_ek[off + c - 128];
        }
        xt[c * ASTR + r] = tf32r(v);
    }
    // fill band matrix: wb[il][r] = w(ibase+il, r-il), 0 outside band
    for (int idx = tid; idx < TI2 * KP; idx += 256) {
        int il = idx / KP, r = idx - il * KP;
        int jo = r - il;
        float v = 0.f;
        if (jo >= 0 && jo < WSZ) v = g_w[(size_t)(ibase + il) * WSZ + jo];
        wb[il * ASTR + r] = tf32r(v);
    }
    __syncthreads();

    const int lane = tid & 31, w = tid >> 5;
    const int mbase = (w & 1) * 16;          // i-tile of 16
    const int cgrp  = (w >> 1) * 32;         // 32 d-columns for num AND den
    const int t4 = lane >> 2, tq = lane & 3;

    float4 nacc[4], dacc[4];
    #pragma unroll
    for (int i = 0; i < 4; i++) {
        nacc[i] = make_float4(0.f, 0.f, 0.f, 0.f);
        dacc[i] = make_float4(0.f, 0.f, 0.f, 0.f);
    }

    const float* arow0 = &wb[(mbase + t4) * ASTR + tq];
    const float* arow1 = arow0 + 8 * ASTR;
    const int klo = mbase;                   // first valid k for this m-tile
    const int khi = mbase + 144;             // covers il+126 < mbase+16+127
    #pragma unroll 4
    for (int k0 = klo; k0 < khi; k0 += 8) {
        u32 a0 = fb(arow0[k0]),     a2 = fb(arow0[k0 + 4]);
        u32 a1 = fb(arow1[k0]),     a3 = fb(arow1[k0 + 4]);
        #pragma unroll
        for (int nt = 0; nt < 4; nt++) {
            const float* bn = &xt[(cgrp + nt * 8 + t4) * ASTR + k0 + tq];
            const float* bd = bn + 128 * ASTR;
            mma8(nacc[nt], a0, a1, a2, a3, fb(bn[0]), fb(bn[4]));
            mma8(dacc[nt], a0, a1, a2, a3, fb(bd[0]), fb(bd[4]));
        }
    }

    // epilogue: y = sigmoid(q) * (S_num + num)/(S_den + den)
    const int row0 = mbase + t4, row1 = row0 + 8;
    #pragma unroll
    for (int nt = 0; nt < 4; nt++) {
        int db = cgrp + nt * 8 + 2 * tq;
        float2 sn2 = *(const float2*)&ssn[db];
        float2 sd2 = *(const float2*)&ssd[db];
        size_t o0 = (size_t)n * L * D + (size_t)(ibase + row0) * D + db;
        size_t o1 = (size_t)n * L * D + (size_t)(ibase + row1) * D + db;
        float2 sq0 = *(const float2*)&g_sq[o0];
        float2 sq1 = *(const float2*)&g_sq[o1];
        float2 y0, y1;
        y0.x = sq0.x * (sn2.x + nacc[nt].x) / (sd2.x + dacc[nt].x);
        y0.y = sq0.y * (sn2.y + nacc[nt].y) / (sd2.y + dacc[nt].y);
        y1.x = sq1.x * (sn2.x + nacc[nt].z) / (sd2.x + dacc[nt].z);
        y1.y = sq1.y * (sn2.y + nacc[nt].w) / (sd2.y + dacc[nt].w);
        *(float2*)&g_y[o0] = y0;
        *(float2*)&g_y[o1] = y1;
    }
}

// ---------------- K4: output projection via mma.sync tf32 + transpose ----
__global__ void k_out(const float* __restrict__ Wo, const float* __restrict__ bo,
                      float* __restrict__ out) {
    extern __shared__ float sm[];
    float* ys = sm;                 // [64][XS_STR] A (tf32); reused as res [128][65]
    float* wt = sm + 64 * XS_STR;   // [128][XS_STR] B: wt[c_out][d] (tf32)
    const int lbase = blockIdx.x * 64;
    const int n     = blockIdx.y;
    const int tid   = threadIdx.x;

    for (int idx = tid; idx < 64 * 128; idx += 256) {
        int l = idx >> 7, d = idx & 127;
        ys[l * XS_STR + d] = tf32r(g_y[(size_t)n * L * D + (size_t)(lbase + l) * D + d]);
    }
    for (int idx = tid; idx < 128 * 128; idx += 256) {
        int d = idx >> 7, co = idx & 127;
        wt[co * XS_STR + d] = tf32r(Wo[d * 128 + co]);
    }
    __syncthreads();

    const int lane = tid & 31, w = tid >> 5;
    const int mbase = (w & 3) * 16;
    const int nbase = (w >> 2) * 64;
    const int t4 = lane >> 2, tq = lane & 3;

    float4 acc[8];
    #pragma unroll
    for (int i = 0; i < 8; i++) acc[i] = make_float4(0.f, 0.f, 0.f, 0.f);

    const float* arow0 = &ys[(mbase + t4) * XS_STR + tq];
    const float* arow1 = arow0 + 8 * XS_STR;
    #pragma unroll
    for (int k0 = 0; k0 < 128; k0 += 8) {
        u32 a0 = fb(arow0[k0]),     a2 = fb(arow0[k0 + 4]);
        u32 a1 = fb(arow1[k0]),     a3 = fb(arow1[k0 + 4]);
        #pragma unroll
        for (int nt = 0; nt < 8; nt++) {
            const float* bp = &wt[(nbase + nt * 8 + t4) * XS_STR + k0 + tq];
            mma8(acc[nt], a0, a1, a2, a3, fb(bp[0]), fb(bp[4]));
        }
    }
    __syncthreads();   // done with ys as A; reuse as res[c][l] stride 65

    float* res = ys;
    const int row0 = mbase + t4, row1 = row0 + 8;
    #pragma unroll
    for (int nt = 0; nt < 8; nt++) {
        int cb = nbase + nt * 8 + 2 * tq;
        float b0 = bo[cb], b1 = bo[cb + 1];
        res[(cb    ) * 65 + row0] = acc[nt].x + b0;
        res[(cb + 1) * 65 + row0] = acc[nt].y + b1;
        res[(cb    ) * 65 + row1] = acc[nt].z + b0;
        res[(cb + 1) * 65 + row1] = acc[nt].w + b1;
    }
    __syncthreads();

    for (int idx = tid; idx < 128 * 64; idx += 256) {
        int c = idx >> 6, l = idx & 63;
        out[(size_t)n * D * L + (size_t)c * L + lbase + l] = res[c * 65 + l];
    }
}

// ---------------- launch ----------------
extern "C" void kernel_launch(void* const* d_in, const int* in_sizes, int n_in,
                              void* d_out, int out_size) {
    const float* x   = (const float*)d_in[0];
    const float* Wq  = (const float*)d_in[1];
    const float* bq  = (const float*)d_in[2];
    const float* Wk  = (const float*)d_in[3];
    const float* bk  = (const float*)d_in[4];
    const float* Wv  = (const float*)d_in[5];
    const float* bv  = (const float*)d_in[6];
    const float* Wo  = (const float*)d_in[7];
    const float* bo  = (const float*)d_in[8];
    const float* pb  = (const float*)d_in[9];
    float* out = (float*)d_out;

    const int SMEM_GEMM = (64 + 128) * XS_STR * 4;               // 101376 B
    const int SMEM_AFT  = ((256 + TI2) * ASTR + 256) * 4;        // 189952 B

    static bool attr_done = false;
    if (!attr_done) {
        cudaFuncSetAttribute(k_qkv, cudaFuncAttributeMaxDynamicSharedMemorySize, SMEM_GEMM);
        cudaFuncSetAttribute(k_aft, cudaFuncAttributeMaxDynamicSharedMemorySize, SMEM_AFT);
        cudaFuncSetAttribute(k_out, cudaFuncAttributeMaxDynamicSharedMemorySize, SMEM_GEMM);
        attr_done = true;
    }

    k_window<<<L, 128>>>(pb);
    k_qkv<<<dim3(3, L / 64, NB), 256, SMEM_GEMM>>>(x, Wq, bq, Wk, bk, Wv, bv);
    k_sums<<<dim3(NB, 16), 128>>>();
    k_aft<<<dim3(L / TI2, NB), 256, SMEM_AFT>>>();
    k_out<<<dim3(L / 64, NB), 256, SMEM_GEMM>>>(Wo, bo, out);
}

// round 7
// speedup vs baseline: 1.6334x; 1.6334x over previous
#include <cuda_runtime.h>
#include <math.h>

#define NB   32
#define D    128
#define L    2048
#define WIN  63          // half-window: |i-j| <= 63
#define WSZ  127         // window size
#define XS_STR 132       // smem stride for tf32 fragment tiles (k_qkv/k_out)

// k_aft tiling
#define TI   64                  // i-tile
#define JR   (TI + 2*WIN)        // 190 j-rows in union window

typedef unsigned int       u32;
typedef unsigned long long u64;

// ---- f32x2 helpers ----
__device__ __forceinline__ u64 pk2(float lo, float hi) {
    u64 r; asm("mov.b64 %0, {%1,%2};" : "=l"(r) : "f"(lo), "f"(hi)); return r;
}
__device__ __forceinline__ float2 upk2(u64 p) {
    float2 r; asm("mov.b64 {%0,%1}, %2;" : "=f"(r.x), "=f"(r.y) : "l"(p)); return r;
}
__device__ __forceinline__ u64 ffma2(u64 a, u64 b, u64 c) {
    u64 d; asm("fma.rn.f32x2 %0, %1, %2, %3;" : "=l"(d) : "l"(a), "l"(b), "l"(c)); return d;
}

// ---- tf32 helpers ----
__device__ __forceinline__ float tf32r(float v) {
    u32 u; asm("cvt.rna.tf32.f32 %0, %1;" : "=r"(u) : "f"(v));
    return __uint_as_float(u);
}
__device__ __forceinline__ void mma8(float4& d, u32 a0, u32 a1, u32 a2, u32 a3,
                                     u32 b0, u32 b1) {
    asm("mma.sync.aligned.m16n8k8.row.col.f32.tf32.tf32.f32 "
        "{%0,%1,%2,%3},{%4,%5,%6,%7},{%8,%9},{%0,%1,%2,%3};"
        : "+f"(d.x), "+f"(d.y), "+f"(d.z), "+f"(d.w)
        : "r"(a0), "r"(a1), "r"(a2), "r"(a3), "r"(b0), "r"(b1));
}
__device__ __forceinline__ u32 fb(float v) { return __float_as_uint(v); }

// ---------------- scratch (device globals; no allocation) ----------------
__device__ float g_sq [NB*L*D];   // sigmoid(q)
__device__ float g_ek [NB*L*D];   // exp(k)
__device__ float g_ekv[NB*L*D];   // first v, then exp(k)*v (in-place in k_sums)
__device__ float g_y  [NB*L*D];   // y before out-proj
__device__ float g_w  [L*WSZ];    // exp(pos_bias)-1 on the band (0 off-edge)
__device__ float g_partN[16*NB*D];
__device__ float g_partD[16*NB*D];

// ---------------- K0: band weights ----------------
__global__ void k_window(const float* __restrict__ pos_bias) {
    int i  = blockIdx.x;
    int jo = threadIdx.x;
    if (jo < WSZ) {
        int j = i - WIN + jo;
        float val = 0.f;
        if (j >= 0 && j < L) val = expf(pos_bias[(size_t)i * L + j]) - 1.f;
        g_w[i * WSZ + jo] = val;
    }
}

// ---------------- K1: QKV projection via mma.sync tf32 ----------
__global__ void k_qkv(const float* __restrict__ x,
                      const float* __restrict__ Wq, const float* __restrict__ bq,
                      const float* __restrict__ Wk, const float* __restrict__ bk,
                      const float* __restrict__ Wv, const float* __restrict__ bv) {
    extern __shared__ float sm[];
    float* xs = sm;                 // [64][XS_STR]  A: xs[l][c] (tf32)
    float* wt = sm + 64 * XS_STR;   // [128][XS_STR] B: wt[d][c] = W[c][d] (tf32)
    const int proj  = blockIdx.x;
    const int lbase = blockIdx.y * 64;
    const int n     = blockIdx.z;
    const float* Wm = (proj == 0) ? Wq : (proj == 1) ? Wk : Wv;
    const float* bm = (proj == 0) ? bq : (proj == 1) ? bk : bv;
    const int tid = threadIdx.x;

    for (int idx = tid; idx < 128 * 64; idx += 256) {
        int c = idx >> 6, l = idx & 63;
        xs[l * XS_STR + c] = tf32r(x[(size_t)n * D * L + (size_t)c * L + lbase + l]);
    }
    for (int idx = tid; idx < 128 * 128; idx += 256) {
        int c = idx >> 7, d = idx & 127;
        wt[d * XS_STR + c] = tf32r(Wm[c * 128 + d]);
    }
    __syncthreads();

    const int lane = tid & 31, w = tid >> 5;
    const int mbase = (w & 3) * 16;
    const int nbase = (w >> 2) * 64;
    const int t4 = lane >> 2, tq = lane & 3;

    float4 acc[8];
    #pragma unroll
    for (int i = 0; i < 8; i++) acc[i] = make_float4(0.f, 0.f, 0.f, 0.f);

    const float* arow0 = &xs[(mbase + t4) * XS_STR + tq];
    const float* arow1 = arow0 + 8 * XS_STR;
    #pragma unroll
    for (int k0 = 0; k0 < 128; k0 += 8) {
        u32 a0 = fb(arow0[k0]),     a2 = fb(arow0[k0 + 4]);
        u32 a1 = fb(arow1[k0]),     a3 = fb(arow1[k0 + 4]);
        #pragma unroll
        for (int nt = 0; nt < 8; nt++) {
            const float* bp = &wt[(nbase + nt * 8 + t4) * XS_STR + k0 + tq];
            mma8(acc[nt], a0, a1, a2, a3, fb(bp[0]), fb(bp[4]));
        }
    }

    const int row0 = mbase + t4, row1 = row0 + 8;
    #pragma unroll
    for (int nt = 0; nt < 8; nt++) {
        int cb = nbase + nt * 8 + 2 * tq;
        float b0 = bm[cb], b1 = bm[cb + 1];
        float r[4] = {acc[nt].x + b0, acc[nt].y + b1,
                      acc[nt].z + b0, acc[nt].w + b1};
        if (proj == 0) {
            #pragma unroll
            for (int e = 0; e < 4; e++) r[e] = 1.f / (1.f + expf(-r[e]));
        } else if (proj == 1) {
            #pragma unroll
            for (int e = 0; e < 4; e++) r[e] = expf(r[e]);
        }
        float* dst = (proj == 0) ? g_sq : (proj == 1) ? g_ek : g_ekv;
        size_t o0 = (size_t)n * L * D + (size_t)(lbase + row0) * D + cb;
        size_t o1 = (size_t)n * L * D + (size_t)(lbase + row1) * D + cb;
        *(float2*)&dst[o0] = make_float2(r[0], r[1]);
        *(float2*)&dst[o1] = make_float2(r[2], r[3]);
    }
}

// ---------------- K2: partial column sums; ekv = ek*v in place ----------
__global__ void k_sums() {
    const int n = blockIdx.x, chunk = blockIdx.y, d = threadIdx.x;
    float sn = 0.f, sd = 0.f;
    size_t base = (size_t)n * L * D + d;
    const int l0 = chunk * 128;
    for (int l = l0; l < l0 + 128; l++) {
        size_t off = base + (size_t)l * D;
        float e  = g_ek[off];
        float v  = g_ekv[off];
        float ev = e * v;
        g_ekv[off] = ev;
        sn += ev; sd += e;
    }
    g_partN[(chunk * NB + n) * D + d] = sn;
    g_partD[(chunk * NB + n) * D + d] = sd;
}

// ---------------- K3: banded AFT pass, FFMA2, 16 warps, 3-region loop ----
// grid (L/TI=32, NB), 512 threads
// smem = (JR*256 + TI*128 + 256)*4 = 228352 B
__global__ void __launch_bounds__(512, 1) k_aft() {
    extern __shared__ float sm[];
    float* xsm = sm;                       // [190][256]: cols 0..127 ekv, 128..255 ek
    float* wss = sm + JR * 256;            // [64][128] band weights (col 127 padded 0)
    float* ssn = sm + JR * 256 + TI * 128; // [128] S_num
    float* ssd = ssn + 128;                // [128] S_den
    const int n     = blockIdx.y;
    const int ibase = blockIdx.x * TI;
    const int tid   = threadIdx.x;
    const int jlo   = ibase - WIN;

    // fused global-sum reduction (fp32 exact)
    if (tid < 128) {
        float sn = 0.f, sd = 0.f;
        #pragma unroll
        for (int c = 0; c < 16; c++) {
            sn += g_partN[(c * NB + n) * D + tid];
            sd += g_partD[(c * NB + n) * D + tid];
        }
        ssn[tid] = sn; ssd[tid] = sd;
    }

    for (int idx = tid; idx < JR * 256; idx += 512) {
        int r = idx >> 8, c = idx & 255;
        int j = jlo + r;
        float v = 0.f;
        if (j >= 0 && j < L) {
            size_t off = (size_t)n * L * D + (size_t)j * D;
            v = (c < 128) ? g_ekv[off + c] : g_ek[off + c - 128];
        }
        xsm[idx] = v;
    }
    for (int idx = tid; idx < TI * 128; idx += 512) {
        int il = idx >> 7, jo = idx & 127;
        wss[idx] = (jo < WSZ) ? g_w[(size_t)(ibase + il) * WSZ + jo] : 0.f;
    }
    __syncthreads();

    const int tx = tid & 31;      // d-quad: num cols tx*4.., den cols 128+tx*4..
    const int wp_ = tid >> 5;     // 16 warps
    const int i0  = wp_ * 4;      // 4 i per warp

    u64 nacc[4][2], dacc[4][2];
    #pragma unroll
    for (int a = 0; a < 4; a++) { nacc[a][0]=nacc[a][1]=dacc[a][0]=dacc[a][1]=0ull; }

    const float* xb = &xsm[tx * 4];
    const float* wb = &wss[i0 * 128];

    // ---- edge region A: r in [i0, i0+2] (some jo negative) ----
    #pragma unroll
    for (int e = 0; e < 3; e++) {
        int r = i0 + e;
        ulonglong2 xn = *(const ulonglong2*)&xb[r * 256];
        ulonglong2 xd = *(const ulonglong2*)&xb[r * 256 + 128];
        #pragma unroll
        for (int a = 0; a < 4; a++) {
            int jo = e - a;                       // r - (i0+a)
            float w = (jo >= 0) ? wb[a * 128 + jo] : 0.f;
            u64 wv = pk2(w, w);
            nacc[a][0] = ffma2(wv, xn.x, nacc[a][0]);
            nacc[a][1] = ffma2(wv, xn.y, nacc[a][1]);
            dacc[a][0] = ffma2(wv, xd.x, dacc[a][0]);
            dacc[a][1] = ffma2(wv, xd.y, dacc[a][1]);
        }
    }

    // ---- middle region: r in [i0+3, i0+126], all 4 i in-band, no predicates ----
    #pragma unroll 2
    for (int r = i0 + 3; r <= i0 + 126; r++) {
        ulonglong2 xn = *(const ulonglong2*)&xb[r * 256];
        ulonglong2 xd = *(const ulonglong2*)&xb[r * 256 + 128];
        #pragma unroll
        for (int a = 0; a < 4; a++) {
            float w = wb[a * 128 + (r - i0 - a)];
            u64 wv = pk2(w, w);
            nacc[a][0] = ffma2(wv, xn.x, nacc[a][0]);
            nacc[a][1] = ffma2(wv, xn.y, nacc[a][1]);
            dacc[a][0] = ffma2(wv, xd.x, dacc[a][0]);
            dacc[a][1] = ffma2(wv, xd.y, dacc[a][1]);
        }
    }

    // ---- edge region B: r in [i0+127, i0+129] (some jo > 126) ----
    #pragma unroll
    for (int e = 0; e < 3; e++) {
        int r = i0 + 127 + e;
        ulonglong2 xn = *(const ulonglong2*)&xb[r * 256];
        ulonglong2 xd = *(const ulonglong2*)&xb[r * 256 + 128];
        #pragma unroll
        for (int a = 0; a < 4; a++) {
            int jo = 127 + e - a;
            float w = (jo < WSZ) ? wb[a * 128 + jo] : 0.f;
            u64 wv = pk2(w, w);
            nacc[a][0] = ffma2(wv, xn.x, nacc[a][0]);
            nacc[a][1] = ffma2(wv, xn.y, nacc[a][1]);
            dacc[a][0] = ffma2(wv, xd.x, dacc[a][0]);
            dacc[a][1] = ffma2(wv, xd.y, dacc[a][1]);
        }
    }

    // ---- epilogue: y = sigmoid(q) * (S_num + num)/(S_den + den) ----
    const float4 sn4 = *(const float4*)&ssn[tx * 4];
    const float4 sd4 = *(const float4*)&ssd[tx * 4];
    #pragma unroll
    for (int a = 0; a < 4; a++) {
        int i = ibase + i0 + a;
        float2 n01 = upk2(nacc[a][0]), n23 = upk2(nacc[a][1]);
        float2 d01 = upk2(dacc[a][0]), d23 = upk2(dacc[a][1]);
        size_t off = (size_t)n * L * D + (size_t)i * D + tx * 4;
        float4 sq = *(const float4*)&g_sq[off];
        float4 y;
        y.x = sq.x * (sn4.x + n01.x) / (sd4.x + d01.x);
        y.y = sq.y * (sn4.y + n01.y) / (sd4.y + d01.y);
        y.z = sq.z * (sn4.z + n23.x) / (sd4.z + d23.x);
        y.w = sq.w * (sn4.w + n23.y) / (sd4.w + d23.y);
        *(float4*)&g_y[off] = y;
    }
}

// ---------------- K4: output projection via mma.sync tf32 + transpose ----
__global__ void k_out(const float* __restrict__ Wo, const float* __restrict__ bo,
                      float* __restrict__ out) {
    extern __shared__ float sm[];
    float* ys = sm;                 // [64][XS_STR] A (tf32); reused as res [128][65]
    float* wt = sm + 64 * XS_STR;   // [128][XS_STR] B: wt[c_out][d] (tf32)
    const int lbase = blockIdx.x * 64;
    const int n     = blockIdx.y;
    const int tid   = threadIdx.x;

    for (int idx = tid; idx < 64 * 128; idx += 256) {
        int l = idx >> 7, d = idx & 127;
        ys[l * XS_STR + d] = tf32r(g_y[(size_t)n * L * D + (size_t)(lbase + l) * D + d]);
    }
    for (int idx = tid; idx < 128 * 128; idx += 256) {
        int d = idx >> 7, co = idx & 127;
        wt[co * XS_STR + d] = tf32r(Wo[d * 128 + co]);
    }
    __syncthreads();

    const int lane = tid & 31, w = tid >> 5;
    const int mbase = (w & 3) * 16;
    const int nbase = (w >> 2) * 64;
    const int t4 = lane >> 2, tq = lane & 3;

    float4 acc[8];
    #pragma unroll
    for (int i = 0; i < 8; i++) acc[i] = make_float4(0.f, 0.f, 0.f, 0.f);

    const float* arow0 = &ys[(mbase + t4) * XS_STR + tq];
    const float* arow1 = arow0 + 8 * XS_STR;
    #pragma unroll
    for (int k0 = 0; k0 < 128; k0 += 8) {
        u32 a0 = fb(arow0[k0]),     a2 = fb(arow0[k0 + 4]);
        u32 a1 = fb(arow1[k0]),     a3 = fb(arow1[k0 + 4]);
        #pragma unroll
        for (int nt = 0; nt < 8; nt++) {
            const float* bp = &wt[(nbase + nt * 8 + t4) * XS_STR + k0 + tq];
            mma8(acc[nt], a0, a1, a2, a3, fb(bp[0]), fb(bp[4]));
        }
    }
    __syncthreads();   // done with ys as A; reuse as res[c][l] stride 65

    float* res = ys;
    const int row0 = mbase + t4, row1 = row0 + 8;
    #pragma unroll
    for (int nt = 0; nt < 8; nt++) {
        int cb = nbase + nt * 8 + 2 * tq;
        float b0 = bo[cb], b1 = bo[cb + 1];
        res[(cb    ) * 65 + row0] = acc[nt].x + b0;
        res[(cb + 1) * 65 + row0] = acc[nt].y + b1;
        res[(cb    ) * 65 + row1] = acc[nt].z + b0;
        res[(cb + 1) * 65 + row1] = acc[nt].w + b1;
    }
    __syncthreads();

    for (int idx = tid; idx < 128 * 64; idx += 256) {
        int c = idx >> 6, l = idx & 63;
        out[(size_t)n * D * L + (size_t)c * L + lbase + l] = res[c * 65 + l];
    }
}

// ---------------- launch ----------------
extern "C" void kernel_launch(void* const* d_in, const int* in_sizes, int n_in,
                              void* d_out, int out_size) {
    const float* x   = (const float*)d_in[0];
    const float* Wq  = (const float*)d_in[1];
    const float* bq  = (const float*)d_in[2];
    const float* Wk  = (const float*)d_in[3];
    const float* bk  = (const float*)d_in[4];
    const float* Wv  = (const float*)d_in[5];
    const float* bv  = (const float*)d_in[6];
    const float* Wo  = (const float*)d_in[7];
    const float* bo  = (const float*)d_in[8];
    const float* pb  = (const float*)d_in[9];
    float* out = (float*)d_out;

    const int SMEM_GEMM = (64 + 128) * XS_STR * 4;               // 101376 B
    const int SMEM_AFT  = (JR * 256 + TI * 128 + 256) * 4;       // 228352 B

    static bool attr_done = false;
    if (!attr_done) {
        cudaFuncSetAttribute(k_qkv, cudaFuncAttributeMaxDynamicSharedMemorySize, SMEM_GEMM);
        cudaFuncSetAttribute(k_aft, cudaFuncAttributeMaxDynamicSharedMemorySize, SMEM_AFT);
        cudaFuncSetAttribute(k_out, cudaFuncAttributeMaxDynamicSharedMemorySize, SMEM_GEMM);
        attr_done = true;
    }

    k_window<<<L, 128>>>(pb);
    k_qkv<<<dim3(3, L / 64, NB), 256, SMEM_GEMM>>>(x, Wq, bq, Wk, bk, Wv, bv);
    k_sums<<<dim3(NB, 16), 128>>>();
    k_aft<<<dim3(L / TI, NB), 512, SMEM_AFT>>>();
    k_out<<<dim3(L / 64, NB), 256, SMEM_GEMM>>>(Wo, bo, out);
}

// round 8
// speedup vs baseline: 1.8189x; 1.1136x over previous
#include <cuda_runtime.h>
#include <math.h>

#define NB   32
#define D    128
#define L    2048
#define WIN  63          // half-window: |i-j| <= 63
#define WSZ  127         // window size
#define XS_STR 132       // smem stride for tf32 fragment tiles (k_qkv/k_out)

// k_aft tiling
#define TI   64                  // i-tile
#define JR   (TI + 2*WIN)        // 190 j-rows in union window

typedef unsigned int       u32;
typedef unsigned long long u64;

// ---- f32x2 helpers ----
__device__ __forceinline__ u64 pk2(float lo, float hi) {
    u64 r; asm("mov.b64 %0, {%1,%2};" : "=l"(r) : "f"(lo), "f"(hi)); return r;
}
__device__ __forceinline__ float2 upk2(u64 p) {
    float2 r; asm("mov.b64 {%0,%1}, %2;" : "=f"(r.x), "=f"(r.y) : "l"(p)); return r;
}
__device__ __forceinline__ u64 ffma2(u64 a, u64 b, u64 c) {
    u64 d; asm("fma.rn.f32x2 %0, %1, %2, %3;" : "=l"(d) : "l"(a), "l"(b), "l"(c)); return d;
}

// ---- tf32 helpers ----
__device__ __forceinline__ float tf32r(float v) {
    u32 u; asm("cvt.rna.tf32.f32 %0, %1;" : "=r"(u) : "f"(v));
    return __uint_as_float(u);
}
__device__ __forceinline__ void mma8(float4& d, u32 a0, u32 a1, u32 a2, u32 a3,
                                     u32 b0, u32 b1) {
    asm("mma.sync.aligned.m16n8k8.row.col.f32.tf32.tf32.f32 "
        "{%0,%1,%2,%3},{%4,%5,%6,%7},{%8,%9},{%0,%1,%2,%3};"
        : "+f"(d.x), "+f"(d.y), "+f"(d.z), "+f"(d.w)
        : "r"(a0), "r"(a1), "r"(a2), "r"(a3), "r"(b0), "r"(b1));
}
__device__ __forceinline__ u32 fb(float v) { return __float_as_uint(v); }

// ---------------- scratch (device globals; no allocation) ----------------
__device__ float g_sq [NB*L*D];   // sigmoid(q)
__device__ float g_ek [NB*L*D];   // exp(k)
__device__ float g_ekv[NB*L*D];   // first v, then exp(k)*v (in-place in k_sums)
__device__ float g_y  [NB*L*D];   // y before out-proj
__device__ float g_w  [L*WSZ];    // exp(pos_bias)-1 on the band (0 off-edge)
__device__ float g_partN[16*NB*D];
__device__ float g_partD[16*NB*D];

// ---------------- K0: band weights ----------------
__global__ void k_window(const float* __restrict__ pos_bias) {
    int i  = blockIdx.x;
    int jo = threadIdx.x;
    if (jo < WSZ) {
        int j = i - WIN + jo;
        float val = 0.f;
        if (j >= 0 && j < L) val = expf(pos_bias[(size_t)i * L + j]) - 1.f;
        g_w[i * WSZ + jo] = val;
    }
}

// ---------------- K1: QKV projection via mma.sync tf32 ----------
__global__ void k_qkv(const float* __restrict__ x,
                      const float* __restrict__ Wq, const float* __restrict__ bq,
                      const float* __restrict__ Wk, const float* __restrict__ bk,
                      const float* __restrict__ Wv, const float* __restrict__ bv) {
    extern __shared__ float sm[];
    float* xs = sm;                 // [64][XS_STR]  A: xs[l][c] (tf32)
    float* wt = sm + 64 * XS_STR;   // [128][XS_STR] B: wt[d][c] = W[c][d] (tf32)
    const int proj  = blockIdx.x;
    const int lbase = blockIdx.y * 64;
    const int n     = blockIdx.z;
    const float* Wm = (proj == 0) ? Wq : (proj == 1) ? Wk : Wv;
    const float* bm = (proj == 0) ? bq : (proj == 1) ? bk : bv;
    const int tid = threadIdx.x;

    for (int idx = tid; idx < 128 * 64; idx += 256) {
        int c = idx >> 6, l = idx & 63;
        xs[l * XS_STR + c] = tf32r(x[(size_t)n * D * L + (size_t)c * L + lbase + l]);
    }
    for (int idx = tid; idx < 128 * 128; idx += 256) {
        int c = idx >> 7, d = idx & 127;
        wt[d * XS_STR + c] = tf32r(Wm[c * 128 + d]);
    }
    __syncthreads();

    const int lane = tid & 31, w = tid >> 5;
    const int mbase = (w & 3) * 16;
    const int nbase = (w >> 2) * 64;
    const int t4 = lane >> 2, tq = lane & 3;

    float4 acc[8];
    #pragma unroll
    for (int i = 0; i < 8; i++) acc[i] = make_float4(0.f, 0.f, 0.f, 0.f);

    const float* arow0 = &xs[(mbase + t4) * XS_STR + tq];
    const float* arow1 = arow0 + 8 * XS_STR;
    #pragma unroll
    for (int k0 = 0; k0 < 128; k0 += 8) {
        u32 a0 = fb(arow0[k0]),     a2 = fb(arow0[k0 + 4]);
        u32 a1 = fb(arow1[k0]),     a3 = fb(arow1[k0 + 4]);
        #pragma unroll
        for (int nt = 0; nt < 8; nt++) {
            const float* bp = &wt[(nbase + nt * 8 + t4) * XS_STR + k0 + tq];
            mma8(acc[nt], a0, a1, a2, a3, fb(bp[0]), fb(bp[4]));
        }
    }

    const int row0 = mbase + t4, row1 = row0 + 8;
    #pragma unroll
    for (int nt = 0; nt < 8; nt++) {
        int cb = nbase + nt * 8 + 2 * tq;
        float b0 = bm[cb], b1 = bm[cb + 1];
        float r[4] = {acc[nt].x + b0, acc[nt].y + b1,
                      acc[nt].z + b0, acc[nt].w + b1};
        if (proj == 0) {
            #pragma unroll
            for (int e = 0; e < 4; e++) r[e] = 1.f / (1.f + expf(-r[e]));
        } else if (proj == 1) {
            #pragma unroll
            for (int e = 0; e < 4; e++) r[e] = expf(r[e]);
        }
        float* dst = (proj == 0) ? g_sq : (proj == 1) ? g_ek : g_ekv;
        size_t o0 = (size_t)n * L * D + (size_t)(lbase + row0) * D + cb;
        size_t o1 = (size_t)n * L * D + (size_t)(lbase + row1) * D + cb;
        *(float2*)&dst[o0] = make_float2(r[0], r[1]);
        *(float2*)&dst[o1] = make_float2(r[2], r[3]);
    }
}

// ---------------- K2: partial column sums; ekv = ek*v in place ----------
__global__ void k_sums() {
    const int n = blockIdx.x, chunk = blockIdx.y, d = threadIdx.x;
    float sn = 0.f, sd = 0.f;
    size_t base = (size_t)n * L * D + d;
    const int l0 = chunk * 128;
    for (int l = l0; l < l0 + 128; l++) {
        size_t off = base + (size_t)l * D;
        float e  = g_ek[off];
        float v  = g_ekv[off];
        float ev = e * v;
        g_ekv[off] = ev;
        sn += ev; sd += e;
    }
    g_partN[(chunk * NB + n) * D + d] = sn;
    g_partD[(chunk * NB + n) * D + d] = sd;
}

// ---------------- K3: banded AFT pass, FFMA2, 32 warps x 2 i ----
// grid (L/TI=32, NB), 1024 threads
// smem = (JR*256 + TI*128 + 256)*4 = 228352 B
__global__ void __launch_bounds__(1024, 1) k_aft() {
    extern __shared__ float sm[];
    float* xsm = sm;                       // [190][256]: cols 0..127 ekv, 128..255 ek
    float* wss = sm + JR * 256;            // [64][128] band weights (col 127 padded 0)
    float* ssn = sm + JR * 256 + TI * 128; // [128] S_num
    float* ssd = ssn + 128;                // [128] S_den
    const int n     = blockIdx.y;
    const int ibase = blockIdx.x * TI;
    const int tid   = threadIdx.x;
    const int jlo   = ibase - WIN;

    // fused global-sum reduction (fp32 exact)
    if (tid < 128) {
        float sn = 0.f, sd = 0.f;
        #pragma unroll
        for (int c = 0; c < 16; c++) {
            sn += g_partN[(c * NB + n) * D + tid];
            sd += g_partD[(c * NB + n) * D + tid];
        }
        ssn[tid] = sn; ssd[tid] = sd;
    }

    for (int idx = tid; idx < JR * 256; idx += 1024) {
        int r = idx >> 8, c = idx & 255;
        int j = jlo + r;
        float v = 0.f;
        if (j >= 0 && j < L) {
            size_t off = (size_t)n * L * D + (size_t)j * D;
            v = (c < 128) ? g_ekv[off + c] : g_ek[off + c - 128];
        }
        xsm[idx] = v;
    }
    for (int idx = tid; idx < TI * 128; idx += 1024) {
        int il = idx >> 7, jo = idx & 127;
        wss[idx] = (jo < WSZ) ? g_w[(size_t)(ibase + il) * WSZ + jo] : 0.f;
    }
    __syncthreads();

    const int tx  = tid & 31;     // d-quad: num cols tx*4.., den cols 128+tx*4..
    const int wp_ = tid >> 5;     // 32 warps
    const int i0  = wp_ * 2;      // 2 i per warp

    u64 nacc[2][2], dacc[2][2];
    #pragma unroll
    for (int a = 0; a < 2; a++) { nacc[a][0]=nacc[a][1]=dacc[a][0]=dacc[a][1]=0ull; }

    const float* xb  = &xsm[tx * 4];
    const float* w0p = &wss[ i0      * 128];
    const float* w1p = &wss[(i0 + 1) * 128];

    // ---- edge r = i0: only a=0 in-band (jo=0) ----
    {
        const float* xr = &xb[i0 * 256];
        ulonglong2 xn = *(const ulonglong2*)xr;
        ulonglong2 xd = *(const ulonglong2*)(xr + 128);
        u64 wv = pk2(w0p[0], w0p[0]);
        nacc[0][0] = ffma2(wv, xn.x, nacc[0][0]);
        nacc[0][1] = ffma2(wv, xn.y, nacc[0][1]);
        dacc[0][0] = ffma2(wv, xd.x, dacc[0][0]);
        dacc[0][1] = ffma2(wv, xd.y, dacc[0][1]);
    }

    // ---- middle: r in [i0+1, i0+126], both i in-band, no predicates ----
    {
        const float* xr = &xb[(i0 + 1) * 256];
        const float* wa = &w0p[1];           // jo = r - i0
        const float* wb2 = &w1p[0];          // jo = r - i0 - 1
        #pragma unroll 2
        for (int it = 0; it < 126; it++) {
            ulonglong2 xn = *(const ulonglong2*)xr;
            ulonglong2 xd = *(const ulonglong2*)(xr + 128);
            u64 w0 = pk2(wa[it],  wa[it]);
            u64 w1 = pk2(wb2[it], wb2[it]);
            nacc[0][0] = ffma2(w0, xn.x, nacc[0][0]);
            nacc[0][1] = ffma2(w0, xn.y, nacc[0][1]);
            dacc[0][0] = ffma2(w0, xd.x, dacc[0][0]);
            dacc[0][1] = ffma2(w0, xd.y, dacc[0][1]);
            nacc[1][0] = ffma2(w1, xn.x, nacc[1][0]);
            nacc[1][1] = ffma2(w1, xn.y, nacc[1][1]);
            dacc[1][0] = ffma2(w1, xd.x, dacc[1][0]);
            dacc[1][1] = ffma2(w1, xd.y, dacc[1][1]);
            xr += 256;
        }
    }

    // ---- edge r = i0+127: only a=1 in-band (jo=126) ----
    {
        const float* xr = &xb[(i0 + 127) * 256];
        ulonglong2 xn = *(const ulonglong2*)xr;
        ulonglong2 xd = *(const ulonglong2*)(xr + 128);
        u64 wv = pk2(w1p[126], w1p[126]);
        nacc[1][0] = ffma2(wv, xn.x, nacc[1][0]);
        nacc[1][1] = ffma2(wv, xn.y, nacc[1][1]);
        dacc[1][0] = ffma2(wv, xd.x, dacc[1][0]);
        dacc[1][1] = ffma2(wv, xd.y, dacc[1][1]);
    }

    // ---- epilogue: y = sigmoid(q) * (S_num + num)/(S_den + den) ----
    const float4 sn4 = *(const float4*)&ssn[tx * 4];
    const float4 sd4 = *(const float4*)&ssd[tx * 4];
    #pragma unroll
    for (int a = 0; a < 2; a++) {
        int i = ibase + i0 + a;
        float2 n01 = upk2(nacc[a][0]), n23 = upk2(nacc[a][1]);
        float2 d01 = upk2(dacc[a][0]), d23 = upk2(dacc[a][1]);
        size_t off = (size_t)n * L * D + (size_t)i * D + tx * 4;
        float4 sq = *(const float4*)&g_sq[off];
        float4 y;
        y.x = sq.x * (sn4.x + n01.x) / (sd4.x + d01.x);
        y.y = sq.y * (sn4.y + n01.y) / (sd4.y + d01.y);
        y.z = sq.z * (sn4.z + n23.x) / (sd4.z + d23.x);
        y.w = sq.w * (sn4.w + n23.y) / (sd4.w + d23.y);
        *(float4*)&g_y[off] = y;
    }
}

// ---------------- K4: output projection via mma.sync tf32 + transpose ----
__global__ void k_out(const float* __restrict__ Wo, const float* __restrict__ bo,
                      float* __restrict__ out) {
    extern __shared__ float sm[];
    float* ys = sm;                 // [64][XS_STR] A (tf32); reused as res [128][65]
    float* wt = sm + 64 * XS_STR;   // [128][XS_STR] B: wt[c_out][d] (tf32)
    const int lbase = blockIdx.x * 64;
    const int n     = blockIdx.y;
    const int tid   = threadIdx.x;

    for (int idx = tid; idx < 64 * 128; idx += 256) {
        int l = idx >> 7, d = idx & 127;
        ys[l * XS_STR + d] = tf32r(g_y[(size_t)n * L * D + (size_t)(lbase + l) * D + d]);
    }
    for (int idx = tid; idx < 128 * 128; idx += 256) {
        int d = idx >> 7, co = idx & 127;
        wt[co * XS_STR + d] = tf32r(Wo[d * 128 + co]);
    }
    __syncthreads();

    const int lane = tid & 31, w = tid >> 5;
    const int mbase = (w & 3) * 16;
    const int nbase = (w >> 2) * 64;
    const int t4 = lane >> 2, tq = lane & 3;

    float4 acc[8];
    #pragma unroll
    for (int i = 0; i < 8; i++) acc[i] = make_float4(0.f, 0.f, 0.f, 0.f);

    const float* arow0 = &ys[(mbase + t4) * XS_STR + tq];
    const float* arow1 = arow0 + 8 * XS_STR;
    #pragma unroll
    for (int k0 = 0; k0 < 128; k0 += 8) {
        u32 a0 = fb(arow0[k0]),     a2 = fb(arow0[k0 + 4]);
        u32 a1 = fb(arow1[k0]),     a3 = fb(arow1[k0 + 4]);
        #pragma unroll
        for (int nt = 0; nt < 8; nt++) {
            const float* bp = &wt[(nbase + nt * 8 + t4) * XS_STR + k0 + tq];
            mma8(acc[nt], a0, a1, a2, a3, fb(bp[0]), fb(bp[4]));
        }
    }
    __syncthreads();   // done with ys as A; reuse as res[c][l] stride 65

    float* res = ys;
    const int row0 = mbase + t4, row1 = row0 + 8;
    #pragma unroll
    for (int nt = 0; nt < 8; nt++) {
        int cb = nbase + nt * 8 + 2 * tq;
        float b0 = bo[cb], b1 = bo[cb + 1];
        res[(cb    ) * 65 + row0] = acc[nt].x + b0;
        res[(cb + 1) * 65 + row0] = acc[nt].y + b1;
        res[(cb    ) * 65 + row1] = acc[nt].z + b0;
        res[(cb + 1) * 65 + row1] = acc[nt].w + b1;
    }
    __syncthreads();

    for (int idx = tid; idx < 128 * 64; idx += 256) {
        int c = idx >> 6, l = idx & 63;
        out[(size_t)n * D * L + (size_t)c * L + lbase + l] = res[c * 65 + l];
    }
}

// ---------------- launch ----------------
extern "C" void kernel_launch(void* const* d_in, const int* in_sizes, int n_in,
                              void* d_out, int out_size) {
    const float* x   = (const float*)d_in[0];
    const float* Wq  = (const float*)d_in[1];
    const float* bq  = (const float*)d_in[2];
    const float* Wk  = (const float*)d_in[3];
    const float* bk  = (const float*)d_in[4];
    const float* Wv  = (const float*)d_in[5];
    const float* bv  = (const float*)d_in[6];
    const float* Wo  = (const float*)d_in[7];
    const float* bo  = (const float*)d_in[8];
    const float* pb  = (const float*)d_in[9];
    float* out = (float*)d_out;

    const int SMEM_GEMM = (64 + 128) * XS_STR * 4;               // 101376 B
    const int SMEM_AFT  = (JR * 256 + TI * 128 + 256) * 4;       // 228352 B

    static bool attr_done = false;
    if (!attr_done) {
        cudaFuncSetAttribute(k_qkv, cudaFuncAttributeMaxDynamicSharedMemorySize, SMEM_GEMM);
        cudaFuncSetAttribute(k_aft, cudaFuncAttributeMaxDynamicSharedMemorySize, SMEM_AFT);
        cudaFuncSetAttribute(k_out, cudaFuncAttributeMaxDynamicSharedMemorySize, SMEM_GEMM);
        attr_done = true;
    }

    k_window<<<L, 128>>>(pb);
    k_qkv<<<dim3(3, L / 64, NB), 256, SMEM_GEMM>>>(x, Wq, bq, Wk, bk, Wv, bv);
    k_sums<<<dim3(NB, 16), 128>>>();
    k_aft<<<dim3(L / TI, NB), 1024, SMEM_AFT>>>();
    k_out<<<dim3(L / 64, NB), 256, SMEM_GEMM>>>(Wo, bo, out);
}

// round 9
// speedup vs baseline: 1.9238x; 1.0577x over previous
#include <cuda_runtime.h>
#include <math.h>

#define NB   32
#define D    128
#define L    2048
#define WIN  63          // half-window: |i-j| <= 63
#define WSZ  127         // window size
#define XS_STR 132       // smem stride for tf32 fragment tiles (k_qkv/k_out)

// k_aft tiling
#define TI   64                  // i-tile
#define JR   (TI + 2*WIN)        // 190 j-rows in union window
#define NG   16                  // i-groups per block (4 i each)
#define RSTEPS 130               // r-steps per group (split 65/65 across 2 warps)

typedef unsigned int       u32;
typedef unsigned long long u64;

// ---- f32x2 helpers ----
__device__ __forceinline__ u64 pk2(float lo, float hi) {
    u64 r; asm("mov.b64 %0, {%1,%2};" : "=l"(r) : "f"(lo), "f"(hi)); return r;
}
__device__ __forceinline__ float2 upk2(u64 p) {
    float2 r; asm("mov.b64 {%0,%1}, %2;" : "=f"(r.x), "=f"(r.y) : "l"(p)); return r;
}
__device__ __forceinline__ u64 ffma2(u64 a, u64 b, u64 c) {
    u64 d; asm("fma.rn.f32x2 %0, %1, %2, %3;" : "=l"(d) : "l"(a), "l"(b), "l"(c)); return d;
}

// ---- tf32 helpers ----
__device__ __forceinline__ float tf32r(float v) {
    u32 u; asm("cvt.rna.tf32.f32 %0, %1;" : "=r"(u) : "f"(v));
    return __uint_as_float(u);
}
__device__ __forceinline__ void mma8(float4& d, u32 a0, u32 a1, u32 a2, u32 a3,
                                     u32 b0, u32 b1) {
    asm("mma.sync.aligned.m16n8k8.row.col.f32.tf32.tf32.f32 "
        "{%0,%1,%2,%3},{%4,%5,%6,%7},{%8,%9},{%0,%1,%2,%3};"
        : "+f"(d.x), "+f"(d.y), "+f"(d.z), "+f"(d.w)
        : "r"(a0), "r"(a1), "r"(a2), "r"(a3), "r"(b0), "r"(b1));
}
__device__ __forceinline__ u32 fb(float v) { return __float_as_uint(v); }

// ---------------- scratch (device globals; no allocation) ----------------
__device__ float g_sq [NB*L*D];   // sigmoid(q)
__device__ float g_ek [NB*L*D];   // exp(k)
__device__ float g_ekv[NB*L*D];   // first v, then exp(k)*v (in-place in k_sums)
__device__ float g_y  [NB*L*D];   // y before out-proj
__device__ float g_w  [L*WSZ];    // exp(pos_bias)-1 on the band (0 off-edge)
__device__ float g_partN[16*NB*D];
__device__ float g_partD[16*NB*D];

// ---------------- K0: band weights ----------------
__global__ void k_window(const float* __restrict__ pos_bias) {
    int i  = blockIdx.x;
    int jo = threadIdx.x;
    if (jo < WSZ) {
        int j = i - WIN + jo;
        float val = 0.f;
        if (j >= 0 && j < L) val = expf(pos_bias[(size_t)i * L + j]) - 1.f;
        g_w[i * WSZ + jo] = val;
    }
}

// ---------------- K1: QKV projection via mma.sync tf32 ----------
__global__ void k_qkv(const float* __restrict__ x,
                      const float* __restrict__ Wq, const float* __restrict__ bq,
                      const float* __restrict__ Wk, const float* __restrict__ bk,
                      const float* __restrict__ Wv, const float* __restrict__ bv) {
    extern __shared__ float sm[];
    float* xs = sm;                 // [64][XS_STR]  A: xs[l][c] (tf32)
    float* wt = sm + 64 * XS_STR;   // [128][XS_STR] B: wt[d][c] = W[c][d] (tf32)
    const int proj  = blockIdx.x;
    const int lbase = blockIdx.y * 64;
    const int n     = blockIdx.z;
    const float* Wm = (proj == 0) ? Wq : (proj == 1) ? Wk : Wv;
    const float* bm = (proj == 0) ? bq : (proj == 1) ? bk : bv;
    const int tid = threadIdx.x;

    for (int idx = tid; idx < 128 * 64; idx += 256) {
        int c = idx >> 6, l = idx & 63;
        xs[l * XS_STR + c] = tf32r(x[(size_t)n * D * L + (size_t)c * L + lbase + l]);
    }
    for (int idx = tid; idx < 128 * 128; idx += 256) {
        int c = idx >> 7, d = idx & 127;
        wt[d * XS_STR + c] = tf32r(Wm[c * 128 + d]);
    }
    __syncthreads();

    const int lane = tid & 31, w = tid >> 5;
    const int mbase = (w & 3) * 16;
    const int nbase = (w >> 2) * 64;
    const int t4 = lane >> 2, tq = lane & 3;

    float4 acc[8];
    #pragma unroll
    for (int i = 0; i < 8; i++) acc[i] = make_float4(0.f, 0.f, 0.f, 0.f);

    const float* arow0 = &xs[(mbase + t4) * XS_STR + tq];
    const float* arow1 = arow0 + 8 * XS_STR;
    #pragma unroll
    for (int k0 = 0; k0 < 128; k0 += 8) {
        u32 a0 = fb(arow0[k0]),     a2 = fb(arow0[k0 + 4]);
        u32 a1 = fb(arow1[k0]),     a3 = fb(arow1[k0 + 4]);
        #pragma unroll
        for (int nt = 0; nt < 8; nt++) {
            const float* bp = &wt[(nbase + nt * 8 + t4) * XS_STR + k0 + tq];
            mma8(acc[nt], a0, a1, a2, a3, fb(bp[0]), fb(bp[4]));
        }
    }

    const int row0 = mbase + t4, row1 = row0 + 8;
    #pragma unroll
    for (int nt = 0; nt < 8; nt++) {
        int cb = nbase + nt * 8 + 2 * tq;
        float b0 = bm[cb], b1 = bm[cb + 1];
        float r[4] = {acc[nt].x + b0, acc[nt].y + b1,
                      acc[nt].z + b0, acc[nt].w + b1};
        if (proj == 0) {
            #pragma unroll
            for (int e = 0; e < 4; e++) r[e] = 1.f / (1.f + expf(-r[e]));
        } else if (proj == 1) {
            #pragma unroll
            for (int e = 0; e < 4; e++) r[e] = expf(r[e]);
        }
        float* dst = (proj == 0) ? g_sq : (proj == 1) ? g_ek : g_ekv;
        size_t o0 = (size_t)n * L * D + (size_t)(lbase + row0) * D + cb;
        size_t o1 = (size_t)n * L * D + (size_t)(lbase + row1) * D + cb;
        *(float2*)&dst[o0] = make_float2(r[0], r[1]);
        *(float2*)&dst[o1] = make_float2(r[2], r[3]);
    }
}

// ---------------- K2: partial column sums; ekv = ek*v in place ----------
__global__ void k_sums() {
    const int n = blockIdx.x, chunk = blockIdx.y, d = threadIdx.x;
    float sn = 0.f, sd = 0.f;
    size_t base = (size_t)n * L * D + d;
    const int l0 = chunk * 128;
    for (int l = l0; l < l0 + 128; l++) {
        size_t off = base + (size_t)l * D;
        float e  = g_ek[off];
        float v  = g_ekv[off];
        float ev = e * v;
        g_ekv[off] = ev;
        sn += ev; sd += e;
    }
    g_partN[(chunk * NB + n) * D + d] = sn;
    g_partD[(chunk * NB + n) * D + d] = sd;
}

// ---------------- K3: banded AFT pass: 16 groups x 4 i, r-split x2 ----
// grid (L/TI=32, NB), 1024 threads
// smem = (JR*256 + NG*RSTEPS*4 + 256)*4 = 228864 B
__global__ void __launch_bounds__(1024, 1) k_aft() {
    extern __shared__ float sm[];
    float* xsm = sm;                          // [190][256]: 0..127 ekv, 128..255 ek
    float* wgs = sm + JR * 256;               // [NG][RSTEPS][4] packed band quads
    float* ssn = wgs + NG * RSTEPS * 4;       // [128] S_num
    float* ssd = ssn + 128;                   // [128] S_den
    float* scr = xsm;                         // epilogue scratch (reuses xsm)
    const int n     = blockIdx.y;
    const int ibase = blockIdx.x * TI;
    const int tid   = threadIdx.x;
    const int jlo   = ibase - WIN;

    // fused global-sum reduction (fp32 exact)
    if (tid < 128) {
        float sn = 0.f, sd = 0.f;
        #pragma unroll
        for (int c = 0; c < 16; c++) {
            sn += g_partN[(c * NB + n) * D + tid];
            sd += g_partD[(c * NB + n) * D + tid];
        }
        ssn[tid] = sn; ssd[tid] = sd;
    }

    for (int idx = tid; idx < JR * 256; idx += 1024) {
        int r = idx >> 8, c = idx & 255;
        int j = jlo + r;
        float v = 0.f;
        if (j >= 0 && j < L) {
            size_t off = (size_t)n * L * D + (size_t)j * D;
            v = (c < 128) ? g_ekv[off + c] : g_ek[off + c - 128];
        }
        xsm[idx] = v;
    }
    // packed weight quads: wgs[g][roff][a] = w(ibase+4g+a, roff-a), 0 off-band
    for (int idx = tid; idx < NG * RSTEPS * 4; idx += 1024) {
        int g    = idx / (RSTEPS * 4);
        int rem  = idx - g * (RSTEPS * 4);
        int roff = rem >> 2, a = rem & 3;
        int jo = roff - a;
        float v = 0.f;
        if (jo >= 0 && jo < WSZ)
            v = g_w[(size_t)(ibase + 4 * g + a) * WSZ + jo];
        wgs[idx] = v;
    }
    __syncthreads();

    const int tx   = tid & 31;     // d-quad: num cols tx*4.., den cols 128+tx*4..
    const int wp_  = tid >> 5;     // 32 warps
    const int g    = wp_ >> 1;     // i-group 0..15
    const int half = wp_ & 1;      // r-range half
    const int i0   = g * 4;

    u64 nacc[4][2], dacc[4][2];
    #pragma unroll
    for (int a = 0; a < 4; a++) { nacc[a][0]=nacc[a][1]=dacc[a][0]=dacc[a][1]=0ull; }

    // uniform loop: 65 steps, zero-padded weights handle all edges
    {
        const int roff0 = half * 65;
        const float* xr = &xsm[(i0 + roff0) * 256 + tx * 4];
        const float* wq = &wgs[(g * RSTEPS + roff0) * 4];
        #pragma unroll 2
        for (int it = 0; it < 65; it++) {
            ulonglong2 xn = *(const ulonglong2*)xr;
            ulonglong2 xd = *(const ulonglong2*)(xr + 128);
            float4 wv4 = *(const float4*)wq;
            u64 w0 = pk2(wv4.x, wv4.x);
            u64 w1 = pk2(wv4.y, wv4.y);
            u64 w2 = pk2(wv4.z, wv4.z);
            u64 w3 = pk2(wv4.w, wv4.w);
            nacc[0][0] = ffma2(w0, xn.x, nacc[0][0]);
            nacc[0][1] = ffma2(w0, xn.y, nacc[0][1]);
            dacc[0][0] = ffma2(w0, xd.x, dacc[0][0]);
            dacc[0][1] = ffma2(w0, xd.y, dacc[0][1]);
            nacc[1][0] = ffma2(w1, xn.x, nacc[1][0]);
            nacc[1][1] = ffma2(w1, xn.y, nacc[1][1]);
            dacc[1][0] = ffma2(w1, xd.x, dacc[1][0]);
            dacc[1][1] = ffma2(w1, xd.y, dacc[1][1]);
            nacc[2][0] = ffma2(w2, xn.x, nacc[2][0]);
            nacc[2][1] = ffma2(w2, xn.y, nacc[2][1]);
            dacc[2][0] = ffma2(w2, xd.x, dacc[2][0]);
            dacc[2][1] = ffma2(w2, xd.y, dacc[2][1]);
            nacc[3][0] = ffma2(w3, xn.x, nacc[3][0]);
            nacc[3][1] = ffma2(w3, xn.y, nacc[3][1]);
            dacc[3][0] = ffma2(w3, xd.x, dacc[3][0]);
            dacc[3][1] = ffma2(w3, xd.y, dacc[3][1]);
            xr += 256;
            wq += 4;
        }
    }

    // cross-warp pair reduction via smem scratch (reuse xsm)
    __syncthreads();
    if (half == 1) {
        #pragma unroll
        for (int a = 0; a < 4; a++) {
            float* p = &scr[((g * 4 + a) * 32 + tx) * 8];
            *(ulonglong2*)p       = make_ulonglong2(nacc[a][0], nacc[a][1]);
            *(ulonglong2*)(p + 4) = make_ulonglong2(dacc[a][0], dacc[a][1]);
        }
    }
    __syncthreads();

    if (half == 0) {
        const float4 sn4 = *(const float4*)&ssn[tx * 4];
        const float4 sd4 = *(const float4*)&ssd[tx * 4];
        #pragma unroll
        for (int a = 0; a < 4; a++) {
            const float* p = &scr[((g * 4 + a) * 32 + tx) * 8];
            float4 nb = *(const float4*)p;
            float4 db = *(const float4*)(p + 4);
            float2 n01 = upk2(nacc[a][0]), n23 = upk2(nacc[a][1]);
            float2 d01 = upk2(dacc[a][0]), d23 = upk2(dacc[a][1]);
            int i = ibase + i0 + a;
            size_t off = (size_t)n * L * D + (size_t)i * D + tx * 4;
            float4 sq = *(const float4*)&g_sq[off];
            float4 y;
            y.x = sq.x * (sn4.x + n01.x + nb.x) / (sd4.x + d01.x + db.x);
            y.y = sq.y * (sn4.y + n01.y + nb.y) / (sd4.y + d01.y + db.y);
            y.z = sq.z * (sn4.z + n23.x + nb.z) / (sd4.z + d23.x + db.z);
            y.w = sq.w * (sn4.w + n23.y + nb.w) / (sd4.w + d23.y + db.w);
            *(float4*)&g_y[off] = y;
        }
    }
}

// ---------------- K4: output projection via mma.sync tf32 + transpose ----
__global__ void k_out(const float* __restrict__ Wo, const float* __restrict__ bo,
                      float* __restrict__ out) {
    extern __shared__ float sm[];
    float* ys = sm;                 // [64][XS_STR] A (tf32); reused as res [128][65]
    float* wt = sm + 64 * XS_STR;   // [128][XS_STR] B: wt[c_out][d] (tf32)
    const int lbase = blockIdx.x * 64;
    const int n     = blockIdx.y;
    const int tid   = threadIdx.x;

    for (int idx = tid; idx < 64 * 128; idx += 256) {
        int l = idx >> 7, d = idx & 127;
        ys[l * XS_STR + d] = tf32r(g_y[(size_t)n * L * D + (size_t)(lbase + l) * D + d]);
    }
    for (int idx = tid; idx < 128 * 128; idx += 256) {
        int d = idx >> 7, co = idx & 127;
        wt[co * XS_STR + d] = tf32r(Wo[d * 128 + co]);
    }
    __syncthreads();

    const int lane = tid & 31, w = tid >> 5;
    const int mbase = (w & 3) * 16;
    const int nbase = (w >> 2) * 64;
    const int t4 = lane >> 2, tq = lane & 3;

    float4 acc[8];
    #pragma unroll
    for (int i = 0; i < 8; i++) acc[i] = make_float4(0.f, 0.f, 0.f, 0.f);

    const float* arow0 = &ys[(mbase + t4) * XS_STR + tq];
    const float* arow1 = arow0 + 8 * XS_STR;
    #pragma unroll
    for (int k0 = 0; k0 < 128; k0 += 8) {
        u32 a0 = fb(arow0[k0]),     a2 = fb(arow0[k0 + 4]);
        u32 a1 = fb(arow1[k0]),     a3 = fb(arow1[k0 + 4]);
        #pragma unroll
        for (int nt = 0; nt < 8; nt++) {
            const float* bp = &wt[(nbase + nt * 8 + t4) * XS_STR + k0 + tq];
            mma8(acc[nt], a0, a1, a2, a3, fb(bp[0]), fb(bp[4]));
        }
    }
    __syncthreads();   // done with ys as A; reuse as res[c][l] stride 65

    float* res = ys;
    const int row0 = mbase + t4, row1 = row0 + 8;
    #pragma unroll
    for (int nt = 0; nt < 8; nt++) {
        int cb = nbase + nt * 8 + 2 * tq;
        float b0 = bo[cb], b1 = bo[cb + 1];
        res[(cb    ) * 65 + row0] = acc[nt].x + b0;
        res[(cb + 1) * 65 + row0] = acc[nt].y + b1;
        res[(cb    ) * 65 + row1] = acc[nt].z + b0;
        res[(cb + 1) * 65 + row1] = acc[nt].w + b1;
    }
    __syncthreads();

    for (int idx = tid; idx < 128 * 64; idx += 256) {
        int c = idx >> 6, l = idx & 63;
        out[(size_t)n * D * L + (size_t)c * L + lbase + l] = res[c * 65 + l];
    }
}

// ---------------- launch ----------------
extern "C" void kernel_launch(void* const* d_in, const int* in_sizes, int n_in,
                              void* d_out, int out_size) {
    const float* x   = (const float*)d_in[0];
    const float* Wq  = (const float*)d_in[1];
    const float* bq  = (const float*)d_in[2];
    const float* Wk  = (const float*)d_in[3];
    const float* bk  = (const float*)d_in[4];
    const float* Wv  = (const float*)d_in[5];
    const float* bv  = (const float*)d_in[6];
    const float* Wo  = (const float*)d_in[7];
    const float* bo  = (const float*)d_in[8];
    const float* pb  = (const float*)d_in[9];
    float* out = (float*)d_out;

    const int SMEM_GEMM = (64 + 128) * XS_STR * 4;                     // 101376 B
    const int SMEM_AFT  = (JR * 256 + NG * RSTEPS * 4 + 256) * 4;      // 228864 B

    static bool attr_done = false;
    if (!attr_done) {
        cudaFuncSetAttribute(k_qkv, cudaFuncAttributeMaxDynamicSharedMemorySize, SMEM_GEMM);
        cudaFuncSetAttribute(k_aft, cudaFuncAttributeMaxDynamicSharedMemorySize, SMEM_AFT);
        cudaFuncSetAttribute(k_out, cudaFuncAttributeMaxDynamicSharedMemorySize, SMEM_GEMM);
        attr_done = true;
    }

    k_window<<<L, 128>>>(pb);
    k_qkv<<<dim3(3, L / 64, NB), 256, SMEM_GEMM>>>(x, Wq, bq, Wk, bk, Wv, bv);
    k_sums<<<dim3(NB, 16), 128>>>();
    k_aft<<<dim3(L / TI, NB), 1024, SMEM_AFT>>>();
    k_out<<<dim3(L / 64, NB), 256, SMEM_GEMM>>>(Wo, bo, out);
}